// round 14
// baseline (speedup 1.0000x reference)
#include <cuda_runtime.h>

// GrassmannNN: SITE=8, DIM=16, D=32, B=8192.
// ONE kernel: 8 clusters x 8 blocks (256 thr). Phases chained by HW cluster
// barriers (no global spins, no extra launches):
//   1. per-cluster distributed M build (rank r -> 28 body_w slabs via smem)
//      + per-block row-pattern prefetch
//   2. cluster barrier; load full M (28KB) to smem
//   3. per-cluster full 256-pattern forward (4 patterns/warp, {q,q+64,q+128,
//      q+192} so layers 0-4 share coefficients) -> per-cluster global table
//   4. cluster barrier; load table (32KB) to smem; gather 128 rows/block

__device__ float g_Mc[8 * 7168];                // per-cluster M copies
__device__ __align__(16) float g_Tc[8 * 8192];  // per-cluster pattern tables

// dynamic smem layout (float offsets)
#define SH_SLAB 0          // 28 slabs x 1024 = 28672   (phase 1)
#define SH_M    0          // 7168                      (phases 2-3, reuse)
#define SH_T    7168       // 8192                      (phase 4)
#define SH_EMB  28672      // 256
#define SH_HW   28928      // 1024
#define SH_H    29952      // 32
#define SH_P    29984      // 128 ints (as float slots)
#define SH_FLOATS 30112

__global__ void __launch_bounds__(256, 1)
__cluster_dims__(8, 1, 1)
grassmann_kernel(const int* __restrict__ data,
                 const float* __restrict__ emb,
                 const float* __restrict__ head_w,
                 const float* __restrict__ body_w,
                 float4* __restrict__ out) {
    extern __shared__ float sh[];
    int* shP = reinterpret_cast<int*>(sh + SH_P);
    const int t = threadIdx.x;
    const int c = blockIdx.x >> 3;              // cluster 0..7
    const int r = blockIdx.x & 7;               // rank in cluster
    float* Mc = g_Mc + c * 7168;
    float* Tc = g_Tc + c * 8192;

    // ================= phase 1: stage + build ============================
    {   // 28 contiguous slabs: body_w[r*28672 .. +28672)
        const float4* g4 = reinterpret_cast<const float4*>(body_w + (size_t)r * 28672);
        float4* s4 = reinterpret_cast<float4*>(sh + SH_SLAB);
#pragma unroll
        for (int j = 0; j < 28; ++j)
            s4[t + j * 256] = g4[t + j * 256];
        if (t < 64)
            reinterpret_cast<float4*>(sh + SH_EMB)[t] =
                reinterpret_cast<const float4*>(emb)[t];
        reinterpret_cast<float4*>(sh + SH_HW)[t] =
            reinterpret_cast<const float4*>(head_w)[t];
    }
    // row-pattern prefetch: 128 rows per block
    if (t < 128) {
        const int4* d4 = reinterpret_cast<const int4*>(data + (blockIdx.x * 128 + t) * 8);
        const int4 a = __ldg(d4);
        const int4 b = __ldg(d4 + 1);
        shP[t] = a.x | (a.y << 1) | (a.z << 2) | (a.w << 3)
               | (b.x << 4) | (b.y << 5) | (b.z << 6) | (b.w << 7);
    }
    __syncthreads();

    // head vectors (per-block local copy)
    if (t < 32) {
        const int bit = t >> 4, j = t & 15;
        const float* e = sh + SH_EMB + bit * 16;         // embedding[0][bit]
        float acc = 0.f;
#pragma unroll
        for (int k = 0; k < 16; ++k)
            acc = fmaf(e[k], sh[SH_HW + (bit * 16 + k) * 32 + bit * 16 + j], acc);
        sh[SH_H + t] = tanhf(acc);
    }

    // this rank's 896 M entries -> per-cluster global M
    for (int o = t; o < 896; o += 256) {
        const int slab = o >> 5;
        const int u = o & 31;
        const int bit = u >> 4, k = u & 15;
        const int sid = r * 28 + slab;                   // global slab 0..223
        const int l = sid >> 5, ig = sid & 31;
        const int s1 = ig >> 4, i = ig & 15;
        const int s = bit ? (1 - s1) : s1;
        const float* e = sh + SH_EMB + ((l + 1) * 2 + bit) * 16;
        const float* gs = sh + SH_SLAB + slab * 1024 + bit * 512 + s * 16 + k;
        float acc = 0.f;
#pragma unroll
        for (int j = 0; j < 16; ++j)
            acc = fmaf(e[j], gs[j * 32], acc);
        if (bit == 1 && s == 0) acc = -acc;
        Mc[(((l * 2 + bit) * 2 + s) * 16 + i) * 16 + k] = acc;
    }

    __threadfence();
    asm volatile("barrier.cluster.arrive.aligned;" ::: "memory");
    asm volatile("barrier.cluster.wait.aligned;" ::: "memory");

    // ================= phase 2: M -> smem ================================
    {
        const float4* g4 = reinterpret_cast<const float4*>(Mc);
        float4* s4 = reinterpret_cast<float4*>(sh + SH_M);
#pragma unroll
        for (int j = 0; j < 7; ++j)
            s4[t + j * 256] = g4[t + j * 256];
    }
    __syncthreads();

    // ================= phase 3: 4 patterns per warp ======================
    {
        const int lane = t & 31;
        const int w = t >> 5;
        const int s = lane >> 4, k = lane & 15;
        const int base = r * 8 + w * 1 + 0;   // base in [0,64): r*8 + w
        // patterns: base, base+64, base+128, base+192 (bits6,7 = v)
        const int bit0 = base & 1;
        const float h0 = sh[SH_H + bit0 * 16 + k];
        float u0 = (s == bit0) ? h0 : 0.f;
        float u1 = u0, u2 = u0, u3 = u0;

        float ma[16], mb[16];
#pragma unroll
        for (int l = 0; l < 7; ++l) {
            if (l < 5) {
                const int bit = (base >> (l + 1)) & 1;
                const float* Mp = sh + SH_M + ((l * 2 + bit) * 2 + s) * 256 + k;
#pragma unroll
                for (int i = 0; i < 16; ++i) ma[i] = Mp[i * 16];
                const int src = (bit ? (1 - s) : s) << 4;
                float a0 = 0.f, a1 = 0.f, a2 = 0.f, a3 = 0.f;
#pragma unroll
                for (int i = 0; i < 16; ++i) {
                    a0 = fmaf(__shfl_sync(0xffffffffu, u0, src + i), ma[i], a0);
                    a1 = fmaf(__shfl_sync(0xffffffffu, u1, src + i), ma[i], a1);
                    a2 = fmaf(__shfl_sync(0xffffffffu, u2, src + i), ma[i], a2);
                    a3 = fmaf(__shfl_sync(0xffffffffu, u3, src + i), ma[i], a3);
                }
                u0 = tanhf(a0); u1 = tanhf(a1); u2 = tanhf(a2); u3 = tanhf(a3);
            } else {
                // l=5: bit = v&1 ; l=6: bit = v>>1
                const float* M0 = sh + SH_M + ((l * 2 + 0) * 2 + s) * 256 + k;
                const float* M1 = sh + SH_M + ((l * 2 + 1) * 2 + s) * 256 + k;
#pragma unroll
                for (int i = 0; i < 16; ++i) { ma[i] = M0[i * 16]; mb[i] = M1[i * 16]; }
                const int src0 = s << 4;            // bit=0 path
                const int src1 = (1 - s) << 4;      // bit=1 path
                float a0 = 0.f, a1 = 0.f, a2 = 0.f, a3 = 0.f;
                if (l == 5) {                       // v&1: u0,u2 bit0; u1,u3 bit1
#pragma unroll
                    for (int i = 0; i < 16; ++i) {
                        a0 = fmaf(__shfl_sync(0xffffffffu, u0, src0 + i), ma[i], a0);
                        a2 = fmaf(__shfl_sync(0xffffffffu, u2, src0 + i), ma[i], a2);
                        a1 = fmaf(__shfl_sync(0xffffffffu, u1, src1 + i), mb[i], a1);
                        a3 = fmaf(__shfl_sync(0xffffffffu, u3, src1 + i), mb[i], a3);
                    }
                } else {                            // v>>1: u0,u1 bit0; u2,u3 bit1
#pragma unroll
                    for (int i = 0; i < 16; ++i) {
                        a0 = fmaf(__shfl_sync(0xffffffffu, u0, src0 + i), ma[i], a0);
                        a1 = fmaf(__shfl_sync(0xffffffffu, u1, src0 + i), ma[i], a1);
                        a2 = fmaf(__shfl_sync(0xffffffffu, u2, src1 + i), mb[i], a2);
                        a3 = fmaf(__shfl_sync(0xffffffffu, u3, src1 + i), mb[i], a3);
                    }
                }
                u0 = tanhf(a0); u1 = tanhf(a1); u2 = tanhf(a2); u3 = tanhf(a3);
            }
        }
        const int col = s * 16 + k;
        Tc[(base)       * 32 + col] = u0;
        Tc[(base + 64)  * 32 + col] = u1;
        Tc[(base + 128) * 32 + col] = u2;
        Tc[(base + 192) * 32 + col] = u3;
    }

    __threadfence();
    asm volatile("barrier.cluster.arrive.aligned;" ::: "memory");
    asm volatile("barrier.cluster.wait.aligned;" ::: "memory");

    // ================= phase 4: table -> smem, gather ====================
    {
        const float4* g4 = reinterpret_cast<const float4*>(Tc);
        float4* s4 = reinterpret_cast<float4*>(sh + SH_T);
#pragma unroll
        for (int j = 0; j < 8; ++j)
            s4[t + j * 256] = g4[t + j * 256];
    }
    __syncthreads();

    {
        const float4* T4 = reinterpret_cast<const float4*>(sh + SH_T);
        float4* o4 = out + (size_t)blockIdx.x * 2048;    // 128 rows x 16
#pragma unroll
        for (int j = 0; j < 8; ++j) {
            const int f = t + j * 256;
            const int row = f >> 4, q = f & 15;
            const int p = shP[row];
            const int sec = q >> 2;              // 0:s0-live 1,2:zero 3:s1-live
            float4 v = make_float4(0.f, 0.f, 0.f, 0.f);
            if (sec == 0)      v = T4[p * 8 + (q & 3)];
            else if (sec == 3) v = T4[p * 8 + 4 + (q & 3)];
            o4[f] = v;
        }
    }
}

extern "C" void kernel_launch(void* const* d_in, const int* in_sizes, int n_in,
                              void* d_out, int out_size) {
    const int*   data      = (const int*)d_in[0];    // (8192, 8) int32
    const float* embedding = (const float*)d_in[1];  // (8, 2, 16)
    const float* head_w    = (const float*)d_in[2];  // (32, 32)
    const float* body_w    = (const float*)d_in[3];  // (7, 32, 32, 32)

    static int smem_set = 0;
    if (!smem_set) {
        cudaFuncSetAttribute(grassmann_kernel,
                             cudaFuncAttributeMaxDynamicSharedMemorySize,
                             SH_FLOATS * 4);
        smem_set = 1;
    }

    grassmann_kernel<<<64, 256, SH_FLOATS * 4>>>(
        data, embedding, head_w, body_w, (float4*)d_out);
}